// round 9
// baseline (speedup 1.0000x reference)
#include <cuda_runtime.h>
#include <math.h>

#define BSZ 4096
#define DIM 128

// Scratch: 64MB similarity matrix (L2-resident) + per-row partials.
__device__ float g_S[(size_t)BSZ * BSZ];
__device__ float g_row[BSZ];
__device__ int   g_valid[BSZ];

// ---------------- packed fp32x2 helpers (Blackwell FFMA2) ----------------
__device__ __forceinline__ unsigned long long ffma2(unsigned long long a,
                                                    unsigned long long b,
                                                    unsigned long long c) {
    unsigned long long d;
    asm("fma.rn.f32x2 %0, %1, %2, %3;" : "=l"(d) : "l"(a), "l"(b), "l"(c));
    return d;
}
__device__ __forceinline__ unsigned long long pack2(float lo, float hi) {
    unsigned long long d;
    asm("mov.b64 %0, {%1, %2};" : "=l"(d) : "f"(lo), "f"(hi));
    return d;
}
__device__ __forceinline__ float2 unpack2(unsigned long long v) {
    float2 r;
    asm("mov.b64 {%0, %1}, %2;" : "=f"(r.x), "=f"(r.y) : "l"(v));
    return r;
}

// ---------------- Kernel 1: S = F * F^T, upper-triangular tiles only ------
#define KC 16
#define SROW 132  // padded smem row stride (floats), conflict-free

__global__ __launch_bounds__(256) void gemm_kernel(const float* __restrict__ F) {
    __shared__ float As[KC * SROW];
    __shared__ float Bs[KC * SROW];

    const int tid = threadIdx.x;
    const int tx = tid & 15;
    const int ty = tid >> 4;

    // Map linear block id -> (bi, bj) with bi <= bj over 32x32 tile grid.
    int t = blockIdx.x;
    int bi = (int)(32.5f - sqrtf(32.5f * 32.5f - 2.0f * (float)t));
    while (bi > 0 && bi * 32 - bi * (bi - 1) / 2 > t) bi--;
    while ((bi + 1) * 32 - (bi + 1) * bi / 2 <= t) bi++;
    const int bj = bi + (t - (bi * 32 - bi * (bi - 1) / 2));
    const int i0 = bi * 128;
    const int j0 = bj * 128;

    unsigned long long acc[8][4];
#pragma unroll
    for (int ii = 0; ii < 8; ii++)
#pragma unroll
        for (int p = 0; p < 4; p++) acc[ii][p] = 0ull;

    for (int k0 = 0; k0 < DIM; k0 += KC) {
        __syncthreads();
#pragma unroll
        for (int tt = 0; tt < 2; tt++) {
            int q  = tid + tt * 256;
            int r  = q >> 2;
            int c4 = q & 3;
            float4 av = *(const float4*)(F + (size_t)(i0 + r) * DIM + k0 + c4 * 4);
            As[(c4 * 4 + 0) * SROW + r] = av.x;
            As[(c4 * 4 + 1) * SROW + r] = av.y;
            As[(c4 * 4 + 2) * SROW + r] = av.z;
            As[(c4 * 4 + 3) * SROW + r] = av.w;
            float4 bv = *(const float4*)(F + (size_t)(j0 + r) * DIM + k0 + c4 * 4);
            Bs[(c4 * 4 + 0) * SROW + r] = bv.x;
            Bs[(c4 * 4 + 1) * SROW + r] = bv.y;
            Bs[(c4 * 4 + 2) * SROW + r] = bv.z;
            Bs[(c4 * 4 + 3) * SROW + r] = bv.w;
        }
        __syncthreads();

#pragma unroll
        for (int kk = 0; kk < KC; kk++) {
            float4 a0 = *(const float4*)&As[kk * SROW + ty * 8];
            float4 a1 = *(const float4*)&As[kk * SROW + ty * 8 + 4];
            float4 b0 = *(const float4*)&Bs[kk * SROW + tx * 8];
            float4 b1 = *(const float4*)&Bs[kk * SROW + tx * 8 + 4];
            unsigned long long bp[4];
            bp[0] = pack2(b0.x, b0.y);
            bp[1] = pack2(b0.z, b0.w);
            bp[2] = pack2(b1.x, b1.y);
            bp[3] = pack2(b1.z, b1.w);
            float aa[8] = {a0.x, a0.y, a0.z, a0.w, a1.x, a1.y, a1.z, a1.w};
#pragma unroll
            for (int ii = 0; ii < 8; ii++) {
                unsigned long long ad = pack2(aa[ii], aa[ii]);
#pragma unroll
                for (int p = 0; p < 4; p++) acc[ii][p] = ffma2(ad, bp[p], acc[ii][p]);
            }
        }
    }

    // Unpack accumulators to an 8x8 register block.
    float a[8][8];
#pragma unroll
    for (int ii = 0; ii < 8; ii++)
#pragma unroll
        for (int p = 0; p < 4; p++) {
            float2 f = unpack2(acc[ii][p]);
            a[ii][2 * p]     = f.x;
            a[ii][2 * p + 1] = f.y;
        }

    // Direct store: block (i0, j0), coalesced float4.
#pragma unroll
    for (int ii = 0; ii < 8; ii++) {
        float* dst = g_S + (size_t)(i0 + ty * 8 + ii) * BSZ + j0 + tx * 8;
        *(float4*)(dst)     = make_float4(a[ii][0], a[ii][1], a[ii][2], a[ii][3]);
        *(float4*)(dst + 4) = make_float4(a[ii][4], a[ii][5], a[ii][6], a[ii][7]);
    }

    // Mirror store: block (j0, i0) = transpose, off-diagonal tiles only.
    if (bi != bj) {
#pragma unroll
        for (int c = 0; c < 8; c++) {
            float* dst = g_S + (size_t)(j0 + tx * 8 + c) * BSZ + i0 + ty * 8;
            *(float4*)(dst)     = make_float4(a[0][c], a[1][c], a[2][c], a[3][c]);
            *(float4*)(dst + 4) = make_float4(a[4][c], a[5][c], a[6][c], a[7][c]);
        }
    }
}

// ---------------- Kernel 2: per-row stats + exact top-200 radix select ----
__device__ __forceinline__ float key2f(unsigned int k) {
    unsigned int u = (k & 0x80000000u) ? (k ^ 0x80000000u) : ~k;
    return __uint_as_float(u);
}

#define CAND_MAX 2048

__global__ __launch_bounds__(256) void row_kernel(const int* __restrict__ labels) {
    __shared__ unsigned int key[BSZ];        // 16 KB
    __shared__ unsigned int cand[CAND_MAX];  // 8 KB (integer-only use)
    __shared__ float rf[256];
    __shared__ int   ri[256];
    __shared__ int   hist[256];
    __shared__ unsigned int s_sel;
    __shared__ int s_krem;
    __shared__ int s_cnt;

    const int tid = threadIdx.x;
    const int i = blockIdx.x;
    const int labi = labels[i];
    const float* srow = g_S + (size_t)i * BSZ;

    // --- load row, build keys, local max (over ALL j, incl. diagonal) ---
    float mx = -1e30f;
#pragma unroll
    for (int t = 0; t < 4; t++) {
        int j4 = tid + t * 256;
        float4 v = ((const float4*)srow)[j4];
        float vs[4] = {v.x, v.y, v.z, v.w};
#pragma unroll
        for (int e = 0; e < 4; e++) {
            float f = vs[e];
            mx = fmaxf(mx, f);
            unsigned int u = __float_as_uint(f);
            key[j4 * 4 + e] = (u & 0x80000000u) ? ~u : (u | 0x80000000u);
        }
    }
    rf[tid] = mx;
    __syncthreads();
    for (int s = 128; s; s >>= 1) {
        if (tid < s) rf[tid] = fmaxf(rf[tid], rf[tid + s]);
        __syncthreads();
    }
    const float smax = rf[0];
    __syncthreads();

    // --- positives pass: sums + zero out same-class keys (incl. diagonal) ---
    float sl = 0.f, se = 0.f;
    int cnt = 0;
#pragma unroll
    for (int t = 0; t < 16; t++) {
        int j = tid + t * 256;
        if (labels[j] == labi) {
            if (j != i) {
                float s = key2f(key[j]);
                float lg = (s - smax) * 10.f;
                sl += lg;
                se += expf(lg);
                cnt++;
            }
            key[j] = 0u;
        }
    }
    rf[tid] = sl; __syncthreads();
    for (int s = 128; s; s >>= 1) { if (tid < s) rf[tid] += rf[tid + s]; __syncthreads(); }
    const float sl_tot = rf[0]; __syncthreads();
    rf[tid] = se; __syncthreads();
    for (int s = 128; s; s >>= 1) { if (tid < s) rf[tid] += rf[tid + s]; __syncthreads(); }
    const float se_tot = rf[0]; __syncthreads();
    ri[tid] = cnt; __syncthreads();
    for (int s = 128; s; s >>= 1) { if (tid < s) ri[tid] += ri[tid + s]; __syncthreads(); }
    const int cnt_tot = ri[0]; __syncthreads();

    // --- pass 0: full histogram on top byte (warp-aggregated atomics) ---
    hist[tid] = 0;
    if (tid == 0) s_cnt = 0;
    __syncthreads();
#pragma unroll
    for (int t = 0; t < 16; t++) {
        unsigned int u = key[tid + t * 256];
        unsigned int b = u >> 24;
        unsigned int m = __match_any_sync(0xFFFFFFFFu, b);
        if ((tid & 31) == (__ffs(m) - 1)) atomicAdd(&hist[b], __popc(m));
    }
    __syncthreads();

    unsigned int prefix = 0;
    int krem = 200;

    // bucket select helper (suffix-sum over hist), done inline per pass
#define SELECT_BUCKET()                                                        \
    do {                                                                       \
        ri[tid] = hist[tid];                                                   \
        __syncthreads();                                                       \
        for (int off = 1; off < 256; off <<= 1) {                              \
            int v = ri[tid];                                                   \
            if (tid + off < 256) v += ri[tid + off];                           \
            __syncthreads();                                                   \
            ri[tid] = v;                                                       \
            __syncthreads();                                                   \
        }                                                                      \
        int above = (tid < 255) ? ri[tid + 1] : 0;                             \
        if (ri[tid] >= krem && above < krem) {                                 \
            s_sel = (unsigned int)tid;                                         \
            s_krem = krem - above;                                             \
        }                                                                      \
        __syncthreads();                                                       \
    } while (0)

    SELECT_BUCKET();
    const unsigned int sel0 = s_sel;
    prefix = sel0 << 24;
    krem = s_krem;
    __syncthreads();

    // --- compact candidates sharing the selected top byte (ints only) ---
#pragma unroll
    for (int t = 0; t < 16; t++) {
        unsigned int u = key[tid + t * 256];
        if ((u >> 24) == sel0) {
            int idx = atomicAdd(&s_cnt, 1);
            if (idx < CAND_MAX) cand[idx] = u;
        }
    }
    __syncthreads();
    const int cnt0 = s_cnt;
    const bool useCand = (cnt0 <= CAND_MAX);
    const int nc = useCand ? cnt0 : 0;
    __syncthreads();

    // --- passes 1..3 over the compacted list (or full fallback) ---
    for (int pass = 1; pass < 4; pass++) {
        const int shift = 24 - 8 * pass;
        const unsigned int maskHi = 0xFFFFFFFFu << (shift + 8);
        hist[tid] = 0;
        __syncthreads();
        if (useCand) {
            for (int t = tid; t < nc; t += 256) {
                unsigned int u = cand[t];
                if (((u ^ prefix) & maskHi) == 0u) {
                    unsigned int b = (u >> shift) & 255;
                    unsigned int m = __match_any_sync(__activemask(), b);
                    if ((tid & 31) == (__ffs(m) - 1)) atomicAdd(&hist[b], __popc(m));
                }
            }
        } else {
#pragma unroll
            for (int t = 0; t < 16; t++) {
                unsigned int u = key[tid + t * 256];
                if (((u ^ prefix) & maskHi) == 0u) {
                    unsigned int b = (u >> shift) & 255;
                    unsigned int m = __match_any_sync(__activemask(), b);
                    if ((tid & 31) == (__ffs(m) - 1)) atomicAdd(&hist[b], __popc(m));
                }
            }
        }
        __syncthreads();
        SELECT_BUCKET();
        prefix |= s_sel << shift;
        krem = s_krem;
        __syncthreads();
    }
    const unsigned int pivot = prefix;

    // --- sum exp over top-200 negatives (fixed-order sweep: deterministic) ---
    float sg = 0.f;
#pragma unroll
    for (int t = 0; t < 16; t++) {
        unsigned int u = key[tid + t * 256];
        if (u > pivot) sg += expf((key2f(u) - smax) * 10.f);
    }
    rf[tid] = sg; __syncthreads();
    for (int s = 128; s; s >>= 1) { if (tid < s) rf[tid] += rf[tid + s]; __syncthreads(); }

    if (tid == 0) {
        float sg_tot = rf[0] + (float)krem * expf((key2f(pivot) - smax) * 10.f);
        float denom = se_tot + sg_tot;
        bool valid = (labi > 0) && (cnt_tot > 0);
        float per = 0.f;
        if (valid) per = -2.f * (sl_tot / (float)cnt_tot - logf(denom));
        g_row[i] = per;
        g_valid[i] = valid ? 1 : 0;
    }
}

// ---------------- Kernel 3: deterministic final reduction -----------------
__global__ __launch_bounds__(256) void finalize_kernel(float* __restrict__ out) {
    __shared__ float rf[256];
    __shared__ int   ri[256];
    const int tid = threadIdx.x;
    float s = 0.f;
    int c = 0;
    for (int j = tid; j < BSZ; j += 256) {
        s += g_row[j];
        c += g_valid[j];
    }
    rf[tid] = s; ri[tid] = c;
    __syncthreads();
    for (int k = 128; k; k >>= 1) {
        if (tid < k) { rf[tid] += rf[tid + k]; ri[tid] += ri[tid + k]; }
        __syncthreads();
    }
    if (tid == 0) out[0] = rf[0] / (float)ri[0];
}

// --------------------------------------------------------------------------
extern "C" void kernel_launch(void* const* d_in, const int* in_sizes, int n_in,
                              void* d_out, int out_size) {
    const float* F = (const float*)d_in[0];       // [4096, 1, 128] fp32
    const int* labels = (const int*)d_in[1];      // [4096] int32
    (void)in_sizes; (void)n_in; (void)out_size;

    gemm_kernel<<<528, 256>>>(F);                  // upper-triangular tiles
    row_kernel<<<BSZ, 256>>>(labels);
    finalize_kernel<<<1, 256>>>((float*)d_out);
}

// round 12
// speedup vs baseline: 1.7417x; 1.7417x over previous
#include <cuda_runtime.h>
#include <math.h>

#define BSZ 4096
#define DIM 128

// Scratch: 64MB similarity matrix (L2-resident) + per-row partials.
__device__ float g_S[(size_t)BSZ * BSZ];
__device__ float g_row[BSZ];
__device__ int   g_valid[BSZ];

// ---------------- packed fp32x2 helpers (Blackwell FFMA2) ----------------
__device__ __forceinline__ unsigned long long ffma2(unsigned long long a,
                                                    unsigned long long b,
                                                    unsigned long long c) {
    unsigned long long d;
    asm("fma.rn.f32x2 %0, %1, %2, %3;" : "=l"(d) : "l"(a), "l"(b), "l"(c));
    return d;
}
__device__ __forceinline__ unsigned long long pack2(float lo, float hi) {
    unsigned long long d;
    asm("mov.b64 %0, {%1, %2};" : "=l"(d) : "f"(lo), "f"(hi));
    return d;
}
__device__ __forceinline__ float2 unpack2(unsigned long long v) {
    float2 r;
    asm("mov.b64 {%0, %1}, %2;" : "=f"(r.x), "=f"(r.y) : "l"(v));
    return r;
}

// ------ Kernel 1: S = F*F^T, upper-triangular tiles (R7 body verbatim) ----
#define KC 16
#define SROW 132

__global__ __launch_bounds__(256) void gemm_kernel(const float* __restrict__ F) {
    __shared__ float As[KC * SROW];
    __shared__ float Bs[KC * SROW];

    if (blockIdx.y > blockIdx.x) return;   // keep bi <= bj only

    const int tid = threadIdx.x;
    const int tx = tid & 15;
    const int ty = tid >> 4;
    const int i0 = blockIdx.y * 128;
    const int j0 = blockIdx.x * 128;

    unsigned long long acc[8][4];
#pragma unroll
    for (int ii = 0; ii < 8; ii++)
#pragma unroll
        for (int p = 0; p < 4; p++) acc[ii][p] = 0ull;

    for (int k0 = 0; k0 < DIM; k0 += KC) {
        __syncthreads();
#pragma unroll
        for (int t = 0; t < 2; t++) {
            int q  = tid + t * 256;
            int r  = q >> 2;
            int c4 = q & 3;
            float4 av = *(const float4*)(F + (size_t)(i0 + r) * DIM + k0 + c4 * 4);
            As[(c4 * 4 + 0) * SROW + r] = av.x;
            As[(c4 * 4 + 1) * SROW + r] = av.y;
            As[(c4 * 4 + 2) * SROW + r] = av.z;
            As[(c4 * 4 + 3) * SROW + r] = av.w;
            float4 bv = *(const float4*)(F + (size_t)(j0 + r) * DIM + k0 + c4 * 4);
            Bs[(c4 * 4 + 0) * SROW + r] = bv.x;
            Bs[(c4 * 4 + 1) * SROW + r] = bv.y;
            Bs[(c4 * 4 + 2) * SROW + r] = bv.z;
            Bs[(c4 * 4 + 3) * SROW + r] = bv.w;
        }
        __syncthreads();

#pragma unroll
        for (int kk = 0; kk < KC; kk++) {
            float4 a0 = *(const float4*)&As[kk * SROW + ty * 8];
            float4 a1 = *(const float4*)&As[kk * SROW + ty * 8 + 4];
            float4 b0 = *(const float4*)&Bs[kk * SROW + tx * 8];
            float4 b1 = *(const float4*)&Bs[kk * SROW + tx * 8 + 4];
            unsigned long long bp[4];
            bp[0] = pack2(b0.x, b0.y);
            bp[1] = pack2(b0.z, b0.w);
            bp[2] = pack2(b1.x, b1.y);
            bp[3] = pack2(b1.z, b1.w);
            float aa[8] = {a0.x, a0.y, a0.z, a0.w, a1.x, a1.y, a1.z, a1.w};
#pragma unroll
            for (int ii = 0; ii < 8; ii++) {
                unsigned long long ad = pack2(aa[ii], aa[ii]);
#pragma unroll
                for (int p = 0; p < 4; p++) acc[ii][p] = ffma2(ad, bp[p], acc[ii][p]);
            }
        }
    }

    // Epilogue identical to R7: stream acc out in order, coalesced.
#pragma unroll
    for (int ii = 0; ii < 8; ii++) {
        size_t base = (size_t)(i0 + ty * 8 + ii) * BSZ + j0 + tx * 8;
#pragma unroll
        for (int p = 0; p < 4; p++) {
            *(float2*)(g_S + base + 2 * p) = unpack2(acc[ii][p]);
        }
    }
}

// ------ Kernel 1b: mirror lower triangle via smem transpose ---------------
__global__ __launch_bounds__(256) void mirror_kernel() {
    __shared__ float ts[128][33];
    const int bx = blockIdx.x, by = blockIdx.y;
    if (by >= bx) return;                 // only strictly-upper source tiles
    const int i0 = by * 128, j0 = bx * 128;
    const int tid = threadIdx.x;

    for (int c = 0; c < 4; c++) {
        __syncthreads();
        // load 32 rows x 128 cols from (i0 + c*32, j0): coalesced, cf smem
#pragma unroll
        for (int k = 0; k < 16; k++) {
            int q = tid + k * 256;        // 0..4095
            int r = q >> 7;               // 0..31
            int col = q & 127;
            ts[col][r] = g_S[(size_t)(i0 + c * 32 + r) * BSZ + j0 + col];
        }
        __syncthreads();
        // write 128 rows x 32 cols to (j0, i0 + c*32): coalesced, cf smem
#pragma unroll
        for (int k = 0; k < 16; k++) {
            int q = tid + k * 256;
            int drow = q >> 5;            // 0..127
            int dcol = q & 31;
            g_S[(size_t)(j0 + drow) * BSZ + i0 + c * 32 + dcol] = ts[drow][dcol];
        }
    }
}

// ---------------- Kernel 2: per-row stats + exact top-200 radix select ----
__device__ __forceinline__ float key2f(unsigned int k) {
    unsigned int u = (k & 0x80000000u) ? (k ^ 0x80000000u) : ~k;
    return __uint_as_float(u);
}

__global__ __launch_bounds__(256) void row_kernel(const int* __restrict__ labels) {
    __shared__ unsigned int key[BSZ];   // 16 KB
    __shared__ float rf[256];
    __shared__ float rf2[256];
    __shared__ int   ri[256];
    __shared__ int   hist[256];
    __shared__ unsigned int s_sel;
    __shared__ int s_krem;

    const int tid = threadIdx.x;
    const int i = blockIdx.x;
    const int labi = labels[i];
    const float* srow = g_S + (size_t)i * BSZ;

    // --- load row, build keys, local max (over ALL j, incl. diagonal) ---
    float mx = -1e30f;
#pragma unroll
    for (int t = 0; t < 4; t++) {
        int j4 = tid + t * 256;
        float4 v = ((const float4*)srow)[j4];
        float vs[4] = {v.x, v.y, v.z, v.w};
#pragma unroll
        for (int e = 0; e < 4; e++) {
            float f = vs[e];
            mx = fmaxf(mx, f);
            unsigned int u = __float_as_uint(f);
            key[j4 * 4 + e] = (u & 0x80000000u) ? ~u : (u | 0x80000000u);
        }
    }
    rf[tid] = mx;
    __syncthreads();
    for (int s = 128; s; s >>= 1) {
        if (tid < s) rf[tid] = fmaxf(rf[tid], rf[tid + s]);
        __syncthreads();
    }
    const float smax = rf[0];
    __syncthreads();

    // --- positives pass: sums + zero out same-class keys (incl. diagonal) ---
    float sl = 0.f, se = 0.f;
    int cnt = 0;
#pragma unroll
    for (int t = 0; t < 16; t++) {
        int j = tid + t * 256;
        if (labels[j] == labi) {
            if (j != i) {
                float s = key2f(key[j]);
                float lg = (s - smax) * 10.f;
                sl += lg;
                se += expf(lg);
                cnt++;
            }
            key[j] = 0u;
        }
    }
    // fused tree reduction (per-array order identical to R7's separate trees)
    rf[tid] = sl; rf2[tid] = se; ri[tid] = cnt;
    __syncthreads();
    for (int s = 128; s; s >>= 1) {
        if (tid < s) {
            rf[tid]  += rf[tid + s];
            rf2[tid] += rf2[tid + s];
            ri[tid]  += ri[tid + s];
        }
        __syncthreads();
    }
    const float sl_tot = rf[0];
    const float se_tot = rf2[0];
    const int   cnt_tot = ri[0];
    __syncthreads();

    // --- 4-pass radix select (plain atomics; warp-0 shfl suffix scan) ---
    unsigned int prefix = 0;
    int krem = 200;
    for (int pass = 0; pass < 4; pass++) {
        const int shift = 24 - 8 * pass;
        const unsigned int maskHi = (pass == 0) ? 0u : (0xFFFFFFFFu << (shift + 8));
        hist[tid] = 0;
        __syncthreads();
#pragma unroll
        for (int t = 0; t < 16; t++) {
            unsigned int u = key[tid + t * 256];
            if (((u ^ prefix) & maskHi) == 0u)
                atomicAdd(&hist[(u >> shift) & 255], 1);
        }
        __syncthreads();
        // warp 0: suffix sums over 256 buckets, pick unique bucket
        if (tid < 32) {
            int h[8], suf[8];
#pragma unroll
            for (int e = 0; e < 8; e++) h[e] = hist[tid * 8 + e];
            int run = 0;
#pragma unroll
            for (int e = 7; e >= 0; e--) { run += h[e]; suf[e] = run; }
            // inclusive suffix scan of per-lane totals across lanes
            int v = run;
#pragma unroll
            for (int off = 1; off < 32; off <<= 1) {
                int o = __shfl_down_sync(0xFFFFFFFFu, v, off);
                if (tid + off < 32) v += o;
            }
            const int carry = v - run;     // sum over lanes > tid
#pragma unroll
            for (int e = 0; e < 8; e++) {
                int S   = suf[e] + carry;                       // >= bucket b
                int Sab = (e < 7) ? (suf[e + 1] + carry) : carry; // > bucket b
                if (S >= krem && Sab < krem) {
                    s_sel = (unsigned int)(tid * 8 + e);
                    s_krem = krem - Sab;
                }
            }
        }
        __syncthreads();
        prefix |= s_sel << shift;
        krem = s_krem;
        __syncthreads();
    }
    const unsigned int pivot = prefix;

    // --- sum exp over top-200 negatives: strictly > pivot, plus krem at pivot ---
    float sg = 0.f;
#pragma unroll
    for (int t = 0; t < 16; t++) {
        unsigned int u = key[tid + t * 256];
        if (u > pivot) sg += expf((key2f(u) - smax) * 10.f);
    }
    rf[tid] = sg; __syncthreads();
    for (int s = 128; s; s >>= 1) { if (tid < s) rf[tid] += rf[tid + s]; __syncthreads(); }

    if (tid == 0) {
        float sg_tot = rf[0] + (float)krem * expf((key2f(pivot) - smax) * 10.f);
        float denom = se_tot + sg_tot;
        bool valid = (labi > 0) && (cnt_tot > 0);
        float per = 0.f;
        if (valid) per = -2.f * (sl_tot / (float)cnt_tot - logf(denom));
        g_row[i] = per;
        g_valid[i] = valid ? 1 : 0;
    }
}

// ---------------- Kernel 3: deterministic final reduction -----------------
__global__ __launch_bounds__(256) void finalize_kernel(float* __restrict__ out) {
    __shared__ float rf[256];
    __shared__ int   ri[256];
    const int tid = threadIdx.x;
    float s = 0.f;
    int c = 0;
    for (int j = tid; j < BSZ; j += 256) {
        s += g_row[j];
        c += g_valid[j];
    }
    rf[tid] = s; ri[tid] = c;
    __syncthreads();
    for (int k = 128; k; k >>= 1) {
        if (tid < k) { rf[tid] += rf[tid + k]; ri[tid] += ri[tid + k]; }
        __syncthreads();
    }
    if (tid == 0) out[0] = rf[0] / (float)ri[0];
}

// --------------------------------------------------------------------------
extern "C" void kernel_launch(void* const* d_in, const int* in_sizes, int n_in,
                              void* d_out, int out_size) {
    const float* F = (const float*)d_in[0];       // [4096, 1, 128] fp32
    const int* labels = (const int*)d_in[1];      // [4096] int32
    (void)in_sizes; (void)n_in; (void)out_size;

    dim3 g(32, 32);
    gemm_kernel<<<g, 256>>>(F);        // upper-triangular tiles only
    mirror_kernel<<<g, 256>>>();       // transpose-copy to lower triangle
    row_kernel<<<BSZ, 256>>>(labels);
    finalize_kernel<<<1, 256>>>((float*)d_out);
}

// round 13
// speedup vs baseline: 2.0525x; 1.1784x over previous
#include <cuda_runtime.h>
#include <cuda_bf16.h>
#include <math.h>

#define BSZ 4096
#define DIM 128

// Scratch (no allocs allowed anywhere).
__device__ float g_S[(size_t)BSZ * BSZ];
__device__ float g_row[BSZ];
__device__ int   g_valid[BSZ];
__device__ __nv_bfloat16 g_Fhi[(size_t)BSZ * DIM];
__device__ __nv_bfloat16 g_Flo[(size_t)BSZ * DIM];
__device__ int g_done;   // zero-init; self-resetting last-block counter

// ---------------- Kernel 0: fp32 -> bf16 hi/lo split ----------------
__global__ __launch_bounds__(256) void convert_kernel(const float* __restrict__ F) {
    int idx = blockIdx.x * 256 + threadIdx.x;      // float4 index, 131072 total
    float4 v = ((const float4*)F)[idx];
    float vs[4] = {v.x, v.y, v.z, v.w};
    __nv_bfloat16 h[4], l[4];
#pragma unroll
    for (int e = 0; e < 4; e++) {
        h[e] = __float2bfloat16(vs[e]);
        l[e] = __float2bfloat16(vs[e] - __bfloat162float(h[e]));
    }
    __nv_bfloat162* ph = (__nv_bfloat162*)g_Fhi + idx * 2;
    __nv_bfloat162* pl = (__nv_bfloat162*)g_Flo + idx * 2;
    ph[0] = __halves2bfloat162(h[0], h[1]);
    ph[1] = __halves2bfloat162(h[2], h[3]);
    pl[0] = __halves2bfloat162(l[0], l[1]);
    pl[1] = __halves2bfloat162(l[2], l[3]);
}

// ---------------- mma.sync helpers (sm_80-era PTX, sm_103-legal) ----------
__device__ __forceinline__ void ldsm4(unsigned& r0, unsigned& r1,
                                      unsigned& r2, unsigned& r3, unsigned addr) {
    asm volatile("ldmatrix.sync.aligned.m8n8.x4.shared.b16 {%0,%1,%2,%3}, [%4];"
                 : "=r"(r0), "=r"(r1), "=r"(r2), "=r"(r3) : "r"(addr));
}
__device__ __forceinline__ void mma16816(float* d, const unsigned* a, const unsigned* b) {
    asm volatile(
        "mma.sync.aligned.m16n8k16.row.col.f32.bf16.bf16.f32 "
        "{%0,%1,%2,%3},{%4,%5,%6,%7},{%8,%9},{%0,%1,%2,%3};"
        : "+f"(d[0]), "+f"(d[1]), "+f"(d[2]), "+f"(d[3])
        : "r"(a[0]), "r"(a[1]), "r"(a[2]), "r"(a[3]), "r"(b[0]), "r"(b[1]));
}

// ------- Kernel 1: S = F F^T via HMMA, bf16 2-term split, fp32 accum ------
// smem tiles: 128 rows x 32 cols bf16, row stride 40 bf16 (80B):
// 80*r mod 128 permutes the 8 16B-banks -> conflict-free ldmatrix.
#define KCH 32
#define TLD 40
#define TILE_ELEMS (128 * TLD)

__global__ __launch_bounds__(256, 2) void gemm_mma_kernel() {
    __shared__ __nv_bfloat16 sAhi[TILE_ELEMS];
    __shared__ __nv_bfloat16 sAlo[TILE_ELEMS];
    __shared__ __nv_bfloat16 sBhi[TILE_ELEMS];
    __shared__ __nv_bfloat16 sBlo[TILE_ELEMS];

    const int tid = threadIdx.x;
    const int wid = tid >> 5;
    const int lane = tid & 31;
    const int i0 = blockIdx.y * 128;
    const int j0 = blockIdx.x * 128;
    const int m_off = (wid >> 2) * 64;   // warp M offset (0/64)
    const int n_off = (wid & 3) * 32;    // warp N offset (0/32/64/96)

    const unsigned baseAhi = (unsigned)__cvta_generic_to_shared(sAhi);
    const unsigned baseAlo = (unsigned)__cvta_generic_to_shared(sAlo);
    const unsigned baseBhi = (unsigned)__cvta_generic_to_shared(sBhi);
    const unsigned baseBlo = (unsigned)__cvta_generic_to_shared(sBlo);

    float acc[4][4][4];
#pragma unroll
    for (int mt = 0; mt < 4; mt++)
#pragma unroll
        for (int nt = 0; nt < 4; nt++)
#pragma unroll
            for (int e = 0; e < 4; e++) acc[mt][nt][e] = 0.f;

    // ldmatrix lane-address components (in bf16 elements)
    const int g = lane >> 3, r = lane & 7;
    const int a_row = ((g & 1) << 3) + r;       // + mt*16 + m_off
    const int a_col = (g >> 1) << 3;            // + ks*16
    const int b_row = ((g >> 1) << 3) + r;      // + ntile*16 + n_off
    const int b_col = (g & 1) << 3;             // + ks*16

    for (int kc = 0; kc < DIM; kc += KCH) {
        __syncthreads();
        // load 4 tiles: 128 rows x 32 cols bf16 = 512 uint4 each, 2/thread
#pragma unroll
        for (int t = 0; t < 2; t++) {
            int idx = tid + t * 256;            // 0..511
            int row = idx >> 2;                 // 0..127
            int c = idx & 3;                    // 16B chunk (8 bf16)
            int sm = row * TLD + c * 8;
            int ga = (i0 + row) * DIM + kc + c * 8;
            int gb = (j0 + row) * DIM + kc + c * 8;
            *(uint4*)(sAhi + sm) = *(const uint4*)(g_Fhi + ga);
            *(uint4*)(sAlo + sm) = *(const uint4*)(g_Flo + ga);
            *(uint4*)(sBhi + sm) = *(const uint4*)(g_Fhi + gb);
            *(uint4*)(sBlo + sm) = *(const uint4*)(g_Flo + gb);
        }
        __syncthreads();

#pragma unroll
        for (int ks = 0; ks < 2; ks++) {
            const int kcol = ks * 16;
            // B fragments: 4 n8-tiles, hi+lo; 2 ldmatrix.x4 each
            unsigned bh[4][2], bl[4][2];
            {
                unsigned off0 = (unsigned)((n_off + b_row) * TLD + kcol + b_col) * 2;
                unsigned off1 = (unsigned)((n_off + 16 + b_row) * TLD + kcol + b_col) * 2;
                ldsm4(bh[0][0], bh[0][1], bh[1][0], bh[1][1], baseBhi + off0);
                ldsm4(bh[2][0], bh[2][1], bh[3][0], bh[3][1], baseBhi + off1);
                ldsm4(bl[0][0], bl[0][1], bl[1][0], bl[1][1], baseBlo + off0);
                ldsm4(bl[2][0], bl[2][1], bl[3][0], bl[3][1], baseBlo + off1);
            }
#pragma unroll
            for (int mt = 0; mt < 4; mt++) {
                unsigned ah[4], al[4];
                unsigned aoff = (unsigned)((m_off + mt * 16 + a_row) * TLD + kcol + a_col) * 2;
                ldsm4(ah[0], ah[1], ah[2], ah[3], baseAhi + aoff);
                ldsm4(al[0], al[1], al[2], al[3], baseAlo + aoff);
#pragma unroll
                for (int nt = 0; nt < 4; nt++) {
                    mma16816(acc[mt][nt], ah, bh[nt]);  // hi*hi
                    mma16816(acc[mt][nt], ah, bl[nt]);  // hi*lo
                    mma16816(acc[mt][nt], al, bh[nt]);  // lo*hi
                }
            }
        }
    }

    // Epilogue: D-frag mapping: d0,d1 -> (row lane/4, col 2*(lane%4)+{0,1}),
    // d2,d3 -> row+8. float2 stores.
    const int dr = lane >> 2;
    const int dc = (lane & 3) * 2;
#pragma unroll
    for (int mt = 0; mt < 4; mt++) {
#pragma unroll
        for (int nt = 0; nt < 4; nt++) {
            size_t base0 = (size_t)(i0 + m_off + mt * 16 + dr) * BSZ + j0 + n_off + nt * 8 + dc;
            *(float2*)(g_S + base0) = make_float2(acc[mt][nt][0], acc[mt][nt][1]);
            *(float2*)(g_S + base0 + 8 * BSZ) = make_float2(acc[mt][nt][2], acc[mt][nt][3]);
        }
    }
}

// ---------------- Kernel 2: per-row stats + exact top-200 radix select ----
__device__ __forceinline__ float key2f(unsigned int k) {
    unsigned int u = (k & 0x80000000u) ? (k ^ 0x80000000u) : ~k;
    return __uint_as_float(u);
}

__global__ __launch_bounds__(256) void row_kernel(const int* __restrict__ labels,
                                                  float* __restrict__ out) {
    __shared__ unsigned int key[BSZ];   // 16 KB
    __shared__ float rf[256];
    __shared__ float rf2[256];
    __shared__ int   ri[256];
    __shared__ int   hist[256];
    __shared__ unsigned int s_sel;
    __shared__ int s_krem;
    __shared__ int s_last;

    const int tid = threadIdx.x;
    const int i = blockIdx.x;
    const int labi = labels[i];
    const float* srow = g_S + (size_t)i * BSZ;

    // --- load row, build keys, local max (over ALL j, incl. diagonal) ---
    float mx = -1e30f;
#pragma unroll
    for (int t = 0; t < 4; t++) {
        int j4 = tid + t * 256;
        float4 v = ((const float4*)srow)[j4];
        float vs[4] = {v.x, v.y, v.z, v.w};
#pragma unroll
        for (int e = 0; e < 4; e++) {
            float f = vs[e];
            mx = fmaxf(mx, f);
            unsigned int u = __float_as_uint(f);
            key[j4 * 4 + e] = (u & 0x80000000u) ? ~u : (u | 0x80000000u);
        }
    }
    rf[tid] = mx;
    __syncthreads();
    for (int s = 128; s; s >>= 1) {
        if (tid < s) rf[tid] = fmaxf(rf[tid], rf[tid + s]);
        __syncthreads();
    }
    const float smax = rf[0];
    __syncthreads();

    // --- positives pass: sums + zero out same-class keys (incl. diagonal) ---
    float sl = 0.f, se = 0.f;
    int cnt = 0;
#pragma unroll
    for (int t = 0; t < 16; t++) {
        int j = tid + t * 256;
        if (labels[j] == labi) {
            if (j != i) {
                float s = key2f(key[j]);
                float lg = (s - smax) * 10.f;
                sl += lg;
                se += expf(lg);
                cnt++;
            }
            key[j] = 0u;
        }
    }
    rf[tid] = sl; rf2[tid] = se; ri[tid] = cnt;
    __syncthreads();
    for (int s = 128; s; s >>= 1) {
        if (tid < s) {
            rf[tid]  += rf[tid + s];
            rf2[tid] += rf2[tid + s];
            ri[tid]  += ri[tid + s];
        }
        __syncthreads();
    }
    const float sl_tot = rf[0];
    const float se_tot = rf2[0];
    const int   cnt_tot = ri[0];
    __syncthreads();

    // --- 4-pass radix select (plain atomics; warp-0 shfl suffix scan) ---
    unsigned int prefix = 0;
    int krem = 200;
    for (int pass = 0; pass < 4; pass++) {
        const int shift = 24 - 8 * pass;
        const unsigned int maskHi = (pass == 0) ? 0u : (0xFFFFFFFFu << (shift + 8));
        hist[tid] = 0;
        __syncthreads();
#pragma unroll
        for (int t = 0; t < 16; t++) {
            unsigned int u = key[tid + t * 256];
            if (((u ^ prefix) & maskHi) == 0u)
                atomicAdd(&hist[(u >> shift) & 255], 1);
        }
        __syncthreads();
        if (tid < 32) {
            int h[8], suf[8];
#pragma unroll
            for (int e = 0; e < 8; e++) h[e] = hist[tid * 8 + e];
            int run = 0;
#pragma unroll
            for (int e = 7; e >= 0; e--) { run += h[e]; suf[e] = run; }
            int v = run;
#pragma unroll
            for (int off = 1; off < 32; off <<= 1) {
                int o = __shfl_down_sync(0xFFFFFFFFu, v, off);
                if (tid + off < 32) v += o;
            }
            const int carry = v - run;
#pragma unroll
            for (int e = 0; e < 8; e++) {
                int S   = suf[e] + carry;
                int Sab = (e < 7) ? (suf[e + 1] + carry) : carry;
                if (S >= krem && Sab < krem) {
                    s_sel = (unsigned int)(tid * 8 + e);
                    s_krem = krem - Sab;
                }
            }
        }
        __syncthreads();
        prefix |= s_sel << shift;
        krem = s_krem;
        __syncthreads();
    }
    const unsigned int pivot = prefix;

    // --- sum exp over top-200 negatives ---
    float sg = 0.f;
#pragma unroll
    for (int t = 0; t < 16; t++) {
        unsigned int u = key[tid + t * 256];
        if (u > pivot) sg += expf((key2f(u) - smax) * 10.f);
    }
    rf[tid] = sg; __syncthreads();
    for (int s = 128; s; s >>= 1) { if (tid < s) rf[tid] += rf[tid + s]; __syncthreads(); }

    if (tid == 0) {
        float sg_tot = rf[0] + (float)krem * expf((key2f(pivot) - smax) * 10.f);
        float denom = se_tot + sg_tot;
        bool valid = (labi > 0) && (cnt_tot > 0);
        float per = 0.f;
        if (valid) per = -2.f * (sl_tot / (float)cnt_tot - logf(denom));
        g_row[i] = per;
        g_valid[i] = valid ? 1 : 0;
        __threadfence();
        int v = atomicAdd(&g_done, 1);
        s_last = (v == BSZ - 1);
    }
    __syncthreads();

    // --- last CTA: deterministic final reduction (fixed-order reads) ---
    if (s_last) {
        if (tid == 0) g_done = 0;   // self-reset for graph replay
        __threadfence();
        float s = 0.f;
        int c = 0;
        for (int j = tid; j < BSZ; j += 256) {
            s += g_row[j];
            c += g_valid[j];
        }
        rf[tid] = s; ri[tid] = c;
        __syncthreads();
        for (int k = 128; k; k >>= 1) {
            if (tid < k) { rf[tid] += rf[tid + k]; ri[tid] += ri[tid + k]; }
            __syncthreads();
        }
        if (tid == 0) out[0] = rf[0] / (float)ri[0];
    }
}

// --------------------------------------------------------------------------
extern "C" void kernel_launch(void* const* d_in, const int* in_sizes, int n_in,
                              void* d_out, int out_size) {
    const float* F = (const float*)d_in[0];       // [4096, 1, 128] fp32
    const int* labels = (const int*)d_in[1];      // [4096] int32
    (void)in_sizes; (void)n_in; (void)out_size;

    convert_kernel<<<512, 256>>>(F);
    dim3 g(32, 32);
    gemm_mma_kernel<<<g, 256>>>();
    row_kernel<<<BSZ, 256>>>(labels, (float*)d_out);
}

// round 14
// speedup vs baseline: 2.1872x; 1.0656x over previous
#include <cuda_runtime.h>
#include <cuda_bf16.h>
#include <math.h>

#define BSZ 4096
#define DIM 128

// Scratch (no allocs allowed anywhere).
__device__ float g_S[(size_t)BSZ * BSZ];
__device__ float g_row[BSZ];
__device__ int   g_valid[BSZ];
__device__ __nv_bfloat16 g_Fhi[(size_t)BSZ * DIM];
__device__ __nv_bfloat16 g_Flo[(size_t)BSZ * DIM];
__device__ int g_done;   // zero-init; self-resetting last-block counter

// ---------------- Kernel 0: fp32 -> bf16 hi/lo split ----------------
__global__ __launch_bounds__(256) void convert_kernel(const float* __restrict__ F) {
    int idx = blockIdx.x * 256 + threadIdx.x;      // float4 index, 131072 total
    float4 v = ((const float4*)F)[idx];
    float vs[4] = {v.x, v.y, v.z, v.w};
    __nv_bfloat16 h[4], l[4];
#pragma unroll
    for (int e = 0; e < 4; e++) {
        h[e] = __float2bfloat16(vs[e]);
        l[e] = __float2bfloat16(vs[e] - __bfloat162float(h[e]));
    }
    __nv_bfloat162* ph = (__nv_bfloat162*)g_Fhi + idx * 2;
    __nv_bfloat162* pl = (__nv_bfloat162*)g_Flo + idx * 2;
    ph[0] = __halves2bfloat162(h[0], h[1]);
    ph[1] = __halves2bfloat162(h[2], h[3]);
    pl[0] = __halves2bfloat162(l[0], l[1]);
    pl[1] = __halves2bfloat162(l[2], l[3]);
}

// ---------------- mma.sync / cp.async helpers (sm_80 PTX, sm_103-legal) ---
__device__ __forceinline__ void ldsm4(unsigned& r0, unsigned& r1,
                                      unsigned& r2, unsigned& r3, unsigned addr) {
    asm volatile("ldmatrix.sync.aligned.m8n8.x4.shared.b16 {%0,%1,%2,%3}, [%4];"
                 : "=r"(r0), "=r"(r1), "=r"(r2), "=r"(r3) : "r"(addr));
}
__device__ __forceinline__ void mma16816(float* d, const unsigned* a, const unsigned* b) {
    asm volatile(
        "mma.sync.aligned.m16n8k16.row.col.f32.bf16.bf16.f32 "
        "{%0,%1,%2,%3},{%4,%5,%6,%7},{%8,%9},{%0,%1,%2,%3};"
        : "+f"(d[0]), "+f"(d[1]), "+f"(d[2]), "+f"(d[3])
        : "r"(a[0]), "r"(a[1]), "r"(a[2]), "r"(a[3]), "r"(b[0]), "r"(b[1]));
}
__device__ __forceinline__ void cp16(unsigned dst, const void* src) {
    asm volatile("cp.async.ca.shared.global [%0], [%1], 16;" :: "r"(dst), "l"(src));
}
__device__ __forceinline__ void cp_commit() {
    asm volatile("cp.async.commit_group;");
}
template <int N>
__device__ __forceinline__ void cp_wait() {
    asm volatile("cp.async.wait_group %0;" :: "n"(N));
}

// ------- Kernel 1: S = F F^T upper-tri via HMMA, bf16 2-term split --------
// smem per stage: 4 arrays of 128 rows x 32 cols bf16, row stride 40 (80B):
// 80*r mod 128 permutes the 8 16B-banks -> conflict-free ldmatrix.
#define KCH 32
#define TLD 40
#define ARR_BYTES (128 * TLD * 2)       // 10240
#define STAGE_BYTES (4 * ARR_BYTES)     // 40960
#define SMEM_GEMM (2 * STAGE_BYTES)     // 81920

__global__ __launch_bounds__(256, 2) void gemm_mma_kernel() {
    extern __shared__ __nv_bfloat16 smem[];

    if (blockIdx.y > blockIdx.x) return;   // upper-triangular tiles only

    const int tid = threadIdx.x;
    const int wid = tid >> 5;
    const int lane = tid & 31;
    const int i0 = blockIdx.y * 128;
    const int j0 = blockIdx.x * 128;
    const int m_off = (wid >> 2) * 64;
    const int n_off = (wid & 3) * 32;

    const unsigned sb = (unsigned)__cvta_generic_to_shared(smem);

    // cp.async load of one k-chunk into one stage (8 x 16B per thread)
    const int l_row = tid >> 1;            // 0..127
    const int l_c   = (tid & 1) * 2;       // chunk pair base {0, 2}
    auto load_chunk = [&](int st, int kc) {
        unsigned base = sb + st * STAGE_BYTES;
#pragma unroll
        for (int cc = 0; cc < 2; cc++) {
            int c = l_c + cc;              // 16B chunk 0..3
            unsigned so = (unsigned)(l_row * TLD + c * 8) * 2;
            int ga = (i0 + l_row) * DIM + kc + c * 8;
            int gb = (j0 + l_row) * DIM + kc + c * 8;
            cp16(base + so,                 g_Fhi + ga);
            cp16(base + ARR_BYTES + so,     g_Flo + ga);
            cp16(base + 2 * ARR_BYTES + so, g_Fhi + gb);
            cp16(base + 3 * ARR_BYTES + so, g_Flo + gb);
        }
        cp_commit();
    };

    float acc[4][4][4];
#pragma unroll
    for (int mt = 0; mt < 4; mt++)
#pragma unroll
        for (int nt = 0; nt < 4; nt++)
#pragma unroll
            for (int e = 0; e < 4; e++) acc[mt][nt][e] = 0.f;

    // ldmatrix lane-address components (bf16 elements)
    const int g = lane >> 3, r = lane & 7;
    const int a_row = ((g & 1) << 3) + r;
    const int a_col = (g >> 1) << 3;
    const int b_row = ((g >> 1) << 3) + r;
    const int b_col = (g & 1) << 3;

    load_chunk(0, 0);

    for (int c = 0; c < 4; c++) {
        const int st = c & 1;
        if (c < 3) {
            load_chunk(st ^ 1, (c + 1) * KCH);
            cp_wait<1>();
        } else {
            cp_wait<0>();
        }
        __syncthreads();

        const unsigned stA = sb + st * STAGE_BYTES;
        const unsigned bAhi = stA;
        const unsigned bAlo = stA + ARR_BYTES;
        const unsigned bBhi = stA + 2 * ARR_BYTES;
        const unsigned bBlo = stA + 3 * ARR_BYTES;

#pragma unroll
        for (int ks = 0; ks < 2; ks++) {
            const int kcol = ks * 16;
            unsigned bh[4][2], bl[4][2];
            {
                unsigned off0 = (unsigned)((n_off + b_row) * TLD + kcol + b_col) * 2;
                unsigned off1 = (unsigned)((n_off + 16 + b_row) * TLD + kcol + b_col) * 2;
                ldsm4(bh[0][0], bh[0][1], bh[1][0], bh[1][1], bBhi + off0);
                ldsm4(bh[2][0], bh[2][1], bh[3][0], bh[3][1], bBhi + off1);
                ldsm4(bl[0][0], bl[0][1], bl[1][0], bl[1][1], bBlo + off0);
                ldsm4(bl[2][0], bl[2][1], bl[3][0], bl[3][1], bBlo + off1);
            }
#pragma unroll
            for (int mt = 0; mt < 4; mt++) {
                unsigned ah[4], al[4];
                unsigned aoff = (unsigned)((m_off + mt * 16 + a_row) * TLD + kcol + a_col) * 2;
                ldsm4(ah[0], ah[1], ah[2], ah[3], bAhi + aoff);
                ldsm4(al[0], al[1], al[2], al[3], bAlo + aoff);
#pragma unroll
                for (int nt = 0; nt < 4; nt++) {
                    mma16816(acc[mt][nt], ah, bh[nt]);  // hi*hi
                    mma16816(acc[mt][nt], ah, bl[nt]);  // hi*lo
                    mma16816(acc[mt][nt], al, bh[nt]);  // lo*hi
                }
            }
        }
        __syncthreads();
    }

    // Epilogue: stream-order stores (no register transpose).
    const int dr = lane >> 2;
    const int dc = (lane & 3) * 2;
#pragma unroll
    for (int mt = 0; mt < 4; mt++) {
#pragma unroll
        for (int nt = 0; nt < 4; nt++) {
            size_t base0 = (size_t)(i0 + m_off + mt * 16 + dr) * BSZ + j0 + n_off + nt * 8 + dc;
            *(float2*)(g_S + base0) = make_float2(acc[mt][nt][0], acc[mt][nt][1]);
            *(float2*)(g_S + base0 + 8 * BSZ) = make_float2(acc[mt][nt][2], acc[mt][nt][3]);
        }
    }
}

// ------ Kernel 1b: mirror lower triangle via smem transpose (R12) ---------
__global__ __launch_bounds__(256) void mirror_kernel() {
    __shared__ float ts[128][33];
    const int bx = blockIdx.x, by = blockIdx.y;
    if (by >= bx) return;                 // only strictly-upper source tiles
    const int i0 = by * 128, j0 = bx * 128;
    const int tid = threadIdx.x;

    for (int c = 0; c < 4; c++) {
        __syncthreads();
#pragma unroll
        for (int k = 0; k < 16; k++) {
            int q = tid + k * 256;
            int r = q >> 7;
            int col = q & 127;
            ts[col][r] = g_S[(size_t)(i0 + c * 32 + r) * BSZ + j0 + col];
        }
        __syncthreads();
#pragma unroll
        for (int k = 0; k < 16; k++) {
            int q = tid + k * 256;
            int drow = q >> 5;
            int dcol = q & 31;
            g_S[(size_t)(j0 + drow) * BSZ + i0 + c * 32 + dcol] = ts[drow][dcol];
        }
    }
}

// ---------------- Kernel 2: per-row stats + exact top-200 radix select ----
__device__ __forceinline__ float key2f(unsigned int k) {
    unsigned int u = (k & 0x80000000u) ? (k ^ 0x80000000u) : ~k;
    return __uint_as_float(u);
}

__global__ __launch_bounds__(256) void row_kernel(const int* __restrict__ labels,
                                                  float* __restrict__ out) {
    __shared__ unsigned int key[BSZ];   // 16 KB
    __shared__ float rf[256];
    __shared__ float rf2[256];
    __shared__ int   ri[256];
    __shared__ int   hist4[4][256];     // 4 sub-histograms (contention split)
    __shared__ unsigned int s_sel;
    __shared__ int s_krem;
    __shared__ int s_last;

    const int tid = threadIdx.x;
    const int wid = tid >> 5;
    const int i = blockIdx.x;
    const int labi = labels[i];
    const float* srow = g_S + (size_t)i * BSZ;

    // --- load row, build keys, local max (over ALL j, incl. diagonal) ---
    float mx = -1e30f;
#pragma unroll
    for (int t = 0; t < 4; t++) {
        int j4 = tid + t * 256;
        float4 v = ((const float4*)srow)[j4];
        float vs[4] = {v.x, v.y, v.z, v.w};
#pragma unroll
        for (int e = 0; e < 4; e++) {
            float f = vs[e];
            mx = fmaxf(mx, f);
            unsigned int u = __float_as_uint(f);
            key[j4 * 4 + e] = (u & 0x80000000u) ? ~u : (u | 0x80000000u);
        }
    }
    rf[tid] = mx;
    __syncthreads();
    for (int s = 128; s; s >>= 1) {
        if (tid < s) rf[tid] = fmaxf(rf[tid], rf[tid + s]);
        __syncthreads();
    }
    const float smax = rf[0];
    __syncthreads();

    // --- positives pass: sums + zero out same-class keys (incl. diagonal) ---
    float sl = 0.f, se = 0.f;
    int cnt = 0;
#pragma unroll
    for (int t = 0; t < 16; t++) {
        int j = tid + t * 256;
        if (labels[j] == labi) {
            if (j != i) {
                float s = key2f(key[j]);
                float lg = (s - smax) * 10.f;
                sl += lg;
                se += expf(lg);
                cnt++;
            }
            key[j] = 0u;
        }
    }
    rf[tid] = sl; rf2[tid] = se; ri[tid] = cnt;
    __syncthreads();
    for (int s = 128; s; s >>= 1) {
        if (tid < s) {
            rf[tid]  += rf[tid + s];
            rf2[tid] += rf2[tid + s];
            ri[tid]  += ri[tid + s];
        }
        __syncthreads();
    }
    const float sl_tot = rf[0];
    const float se_tot = rf2[0];
    const int   cnt_tot = ri[0];
    __syncthreads();

    // --- 4-pass radix select (split histograms; warp-0 shfl suffix scan) ---
    unsigned int prefix = 0;
    int krem = 200;
    for (int pass = 0; pass < 4; pass++) {
        const int shift = 24 - 8 * pass;
        const unsigned int maskHi = (pass == 0) ? 0u : (0xFFFFFFFFu << (shift + 8));
#pragma unroll
        for (int q = 0; q < 4; q++) hist4[q][tid] = 0;
        __syncthreads();
        int* myh = hist4[wid >> 1];
#pragma unroll
        for (int t = 0; t < 16; t++) {
            unsigned int u = key[tid + t * 256];
            if (((u ^ prefix) & maskHi) == 0u)
                atomicAdd(&myh[(u >> shift) & 255], 1);
        }
        __syncthreads();
        if (tid < 32) {
            int h[8], suf[8];
#pragma unroll
            for (int e = 0; e < 8; e++)
                h[e] = hist4[0][tid * 8 + e] + hist4[1][tid * 8 + e]
                     + hist4[2][tid * 8 + e] + hist4[3][tid * 8 + e];
            int run = 0;
#pragma unroll
            for (int e = 7; e >= 0; e--) { run += h[e]; suf[e] = run; }
            int v = run;
#pragma unroll
            for (int off = 1; off < 32; off <<= 1) {
                int o = __shfl_down_sync(0xFFFFFFFFu, v, off);
                if (tid + off < 32) v += o;
            }
            const int carry = v - run;
#pragma unroll
            for (int e = 0; e < 8; e++) {
                int S   = suf[e] + carry;
                int Sab = (e < 7) ? (suf[e + 1] + carry) : carry;
                if (S >= krem && Sab < krem) {
                    s_sel = (unsigned int)(tid * 8 + e);
                    s_krem = krem - Sab;
                }
            }
        }
        __syncthreads();
        prefix |= s_sel << shift;
        krem = s_krem;
        __syncthreads();
    }
    const unsigned int pivot = prefix;

    // --- sum exp over top-200 negatives ---
    float sg = 0.f;
#pragma unroll
    for (int t = 0; t < 16; t++) {
        unsigned int u = key[tid + t * 256];
        if (u > pivot) sg += expf((key2f(u) - smax) * 10.f);
    }
    rf[tid] = sg; __syncthreads();
    for (int s = 128; s; s >>= 1) { if (tid < s) rf[tid] += rf[tid + s]; __syncthreads(); }

    if (tid == 0) {
        float sg_tot = rf[0] + (float)krem * expf((key2f(pivot) - smax) * 10.f);
        float denom = se_tot + sg_tot;
        bool valid = (labi > 0) && (cnt_tot > 0);
        float per = 0.f;
        if (valid) per = -2.f * (sl_tot / (float)cnt_tot - logf(denom));
        g_row[i] = per;
        g_valid[i] = valid ? 1 : 0;
        __threadfence();
        int v = atomicAdd(&g_done, 1);
        s_last = (v == BSZ - 1);
    }
    __syncthreads();

    // --- last CTA: deterministic final reduction (fixed-order reads) ---
    if (s_last) {
        if (tid == 0) g_done = 0;   // self-reset for graph replay
        __threadfence();
        float s = 0.f;
        int c = 0;
        for (int j = tid; j < BSZ; j += 256) {
            s += g_row[j];
            c += g_valid[j];
        }
        rf[tid] = s; ri[tid] = c;
        __syncthreads();
        for (int k = 128; k; k >>= 1) {
            if (tid < k) { rf[tid] += rf[tid + k]; ri[tid] += ri[tid + k]; }
            __syncthreads();
        }
        if (tid == 0) out[0] = rf[0] / (float)ri[0];
    }
}

// --------------------------------------------------------------------------
extern "C" void kernel_launch(void* const* d_in, const int* in_sizes, int n_in,
                              void* d_out, int out_size) {
    const float* F = (const float*)d_in[0];       // [4096, 1, 128] fp32
    const int* labels = (const int*)d_in[1];      // [4096] int32
    (void)in_sizes; (void)n_in; (void)out_size;

    cudaFuncSetAttribute(gemm_mma_kernel,
                         cudaFuncAttributeMaxDynamicSharedMemorySize, SMEM_GEMM);

    convert_kernel<<<512, 256>>>(F);
    dim3 g(32, 32);
    gemm_mma_kernel<<<g, 256, SMEM_GEMM>>>();   // upper-triangular tiles
    mirror_kernel<<<g, 256>>>();                // transpose-copy lower triangle
    row_kernel<<<BSZ, 256>>>(labels, (float*)d_out);
}